// round 1
// baseline (speedup 1.0000x reference)
#include <cuda_runtime.h>

// Problem-fixed shapes (reference setup_inputs):
//   q:           [B=2, C=64, H=192, W=320]            fp32
//   warped_feat: [B=2, C=64, H=192, W=320, D=32]      fp32
//   out (sim):   [B=2, D=32, H=192, W=320]            fp32
#define B_  2
#define C_  64
#define H_  192
#define W_  320
#define D_  32
#define HW_ (H_ * W_)
#define NPIX (B_ * HW_)          // 122880
#define EPS_ 1e-12f

// Scratch: per-pixel channel reductions, d-contiguous layout [pixel][d].
__device__ float g_num[(size_t)NPIX * D_];   // sum_c q*k_d
__device__ float g_kk [(size_t)NPIX * D_];   // sum_c k_d^2
__device__ float g_qq [NPIX];                // sum_c q^2

// ---------------------------------------------------------------------------
// Kernel 1: per-pixel reduction over C. 8 threads per pixel, float4 over d.
// Each warp handles 4 consecutive pixels -> every k load covers a contiguous
// 512B span (4 pixels * 32 d * 4B), fully coalesced LDG.128s.
// ---------------------------------------------------------------------------
__global__ __launch_bounds__(256, 4)
void dav_reduce_c(const float* __restrict__ q, const float* __restrict__ k)
{
    const int tid  = threadIdx.x;
    const int grp  = tid >> 3;        // pixel within block: 0..31
    const int sub  = tid & 7;         // d-quad: 0..7
    const int pix  = blockIdx.x * 32 + grp;     // NPIX divisible by 32

    const int b  = pix / HW_;
    const int hw = pix - b * HW_;

    const float* __restrict__ qp = q + (size_t)b * C_ * HW_ + hw;
    const float* __restrict__ kp = k + ((size_t)b * C_ * HW_ + hw) * D_ + sub * 4;

    float4 num = make_float4(0.f, 0.f, 0.f, 0.f);
    float4 kk  = make_float4(0.f, 0.f, 0.f, 0.f);
    float  qq  = 0.f;

    const size_t kstride = (size_t)HW_ * D_;   // floats between c-planes in k

    #pragma unroll 8
    for (int c = 0; c < C_; ++c) {
        const float  qv = __ldg(qp + (size_t)c * HW_);
        const float4 kv = *reinterpret_cast<const float4*>(kp + (size_t)c * kstride);
        num.x = fmaf(qv, kv.x, num.x);
        num.y = fmaf(qv, kv.y, num.y);
        num.z = fmaf(qv, kv.z, num.z);
        num.w = fmaf(qv, kv.w, num.w);
        kk.x  = fmaf(kv.x, kv.x, kk.x);
        kk.y  = fmaf(kv.y, kv.y, kk.y);
        kk.z  = fmaf(kv.z, kv.z, kk.z);
        kk.w  = fmaf(kv.w, kv.w, kk.w);
        qq    = fmaf(qv, qv, qq);
    }

    const size_t o = (size_t)pix * D_ + sub * 4;
    *reinterpret_cast<float4*>(g_num + o) = num;
    *reinterpret_cast<float4*>(g_kk  + o) = kk;
    if (sub == 0) g_qq[pix] = qq;
}

// ---------------------------------------------------------------------------
// Kernel 2: 3x3 zero-padded box filter + normalize.
// Block = 256 threads = 8 warps = 8 consecutive-w pixels of one row.
// Warp per pixel, lane = d -> coalesced 128B reads of each neighbor's
// pre-reductions. Shared transpose so the [b,d,h,w] output writes are
// contiguous 32B runs per d instead of 32-way scattered 4B stores.
// ---------------------------------------------------------------------------
__global__ __launch_bounds__(256)
void dav_box_norm(float* __restrict__ out)
{
    const int tid  = threadIdx.x;
    const int wpix = tid >> 5;        // pixel within block: 0..7
    const int d    = tid & 31;

    const int pix = blockIdx.x * 8 + wpix;      // W divisible by 8 -> no row straddle
    const int b   = pix / HW_;
    const int hw  = pix - b * HW_;
    const int h   = hw / W_;
    const int w   = hw - h * W_;

    const size_t base = (size_t)b * HW_;

    float num = 0.f, kk = 0.f, qq = 0.f;
    #pragma unroll
    for (int dh = -1; dh <= 1; ++dh) {
        const int hh = h + dh;
        if (hh < 0 || hh >= H_) continue;
        #pragma unroll
        for (int dw = -1; dw <= 1; ++dw) {
            const int ww = w + dw;
            if (ww < 0 || ww >= W_) continue;
            const size_t p = base + (size_t)hh * W_ + ww;
            num += g_num[p * D_ + d];
            kk  += g_kk [p * D_ + d];
            qq  += g_qq[p];
        }
    }

    const float nq  = fmaxf(sqrtf(qq), EPS_);
    const float nk  = fmaxf(sqrtf(kk), EPS_);
    const float sim = num / (nq * nk);

    __shared__ float s[8][33];        // +1 pad: conflict-free transpose
    s[wpix][d] = sim;
    __syncthreads();

    // Write phase: thread t -> (od = t/8, ow = t%8); 8 consecutive w per d.
    const int od = tid >> 3;
    const int ow = tid & 7;
    const int pix0 = blockIdx.x * 8;
    const int b0   = pix0 / HW_;
    const int hw0  = pix0 - b0 * HW_;
    const int h0   = hw0 / W_;
    const int w0   = hw0 - h0 * W_;

    out[(((size_t)b0 * D_ + od) * H_ + h0) * W_ + w0 + ow] = s[ow][od];
}

// ---------------------------------------------------------------------------
extern "C" void kernel_launch(void* const* d_in, const int* in_sizes, int n_in,
                              void* d_out, int out_size)
{
    const float* q = (const float*)d_in[0];              // [B,C,H,W]
    const float* k = (const float*)d_in[1];              // [B,C,H,W,D]
    float* out     = (float*)d_out;                      // [B,D,H,W]

    dav_reduce_c<<<NPIX / 32, 256>>>(q, k);
    dav_box_norm<<<NPIX / 8, 256>>>(out);
}

// round 2
// speedup vs baseline: 1.1008x; 1.1008x over previous
#include <cuda_runtime.h>

// Shapes (fixed by the problem):
//   q:           [B=2, C=64, H=192, W=320]            fp32
//   warped_feat: [B=2, C=64, H=192, W=320, D=32]      fp32
//   out (sim):   [B=2, D=32, H=192, W=320]            fp32
#define B_  2
#define C_  64
#define H_  192
#define W_  320
#define D_  32
#define HW_ (H_ * W_)
#define NPIX (B_ * HW_)            // 122880
#define HP_ (H_ + 2)               // padded
#define WP_ (W_ + 2)
#define PPIX (B_ * HP_ * WP_)      // padded pixel count
#define EPS_ 1e-12f

// Scratch (zero-padded 1-pixel border so the 3x3 box needs no bounds checks).
// g_nk[pp][d] = (num, kk) interleaved -> one LDG.64 fetches both.
__device__ float2 g_nk [(size_t)PPIX * D_];    // 32 MB
__device__ float  g_qqp[PPIX];                 // padded sum_c q^2
__device__ float  g_nqi[NPIX];                 // 1 / max(sqrt(box(qq)), eps)

// ---------------------------------------------------------------------------
// Kernel 0: zero the padded border ring (1028 ring cells per image).
// ---------------------------------------------------------------------------
__global__ void dav_zero_border()
{
    const int t = blockIdx.x * 128 + threadIdx.x;
    if (t >= B_ * 1028) return;
    const int b = t / 1028;
    const int i = t - b * 1028;
    int hp, wp;
    if (i < WP_)          { hp = 0;       wp = i; }
    else if (i < 2 * WP_) { hp = H_ + 1;  wp = i - WP_; }
    else { const int j = i - 2 * WP_;     // j in [0, 2*H)
           hp = 1 + (j >> 1);  wp = (j & 1) ? (W_ + 1) : 0; }

    const size_t pp = ((size_t)b * HP_ + hp) * WP_ + wp;
    float4* o = reinterpret_cast<float4*>(g_nk + pp * D_);
    #pragma unroll
    for (int k = 0; k < 16; ++k) o[k] = make_float4(0.f, 0.f, 0.f, 0.f);
    g_qqp[pp] = 0.f;
}

// ---------------------------------------------------------------------------
// Kernel 1: per-pixel reduction over C (unchanged strategy; ~HBM roofline).
// 8 threads per pixel, float4 over d; writes interleaved (num,kk) float2s
// into the padded scratch.
// ---------------------------------------------------------------------------
__global__ __launch_bounds__(256, 4)
void dav_reduce_c(const float* __restrict__ q, const float* __restrict__ k)
{
    const int tid = threadIdx.x;
    const int grp = tid >> 3;          // pixel within block: 0..31
    const int sub = tid & 7;           // d-quad: 0..7
    const int pix = blockIdx.x * 32 + grp;

    const int b  = pix / HW_;
    const int hw = pix - b * HW_;
    const int h  = hw / W_;
    const int w  = hw - h * W_;

    const float* __restrict__ qp = q + (size_t)b * C_ * HW_ + hw;
    const float* __restrict__ kp = k + ((size_t)b * C_ * HW_ + hw) * D_ + sub * 4;

    float4 num = make_float4(0.f, 0.f, 0.f, 0.f);
    float4 kk  = make_float4(0.f, 0.f, 0.f, 0.f);
    float  qq  = 0.f;

    const size_t kstride = (size_t)HW_ * D_;

    #pragma unroll 8
    for (int c = 0; c < C_; ++c) {
        const float  qv = __ldg(qp + (size_t)c * HW_);
        const float4 kv = *reinterpret_cast<const float4*>(kp + (size_t)c * kstride);
        num.x = fmaf(qv, kv.x, num.x);
        num.y = fmaf(qv, kv.y, num.y);
        num.z = fmaf(qv, kv.z, num.z);
        num.w = fmaf(qv, kv.w, num.w);
        kk.x  = fmaf(kv.x, kv.x, kk.x);
        kk.y  = fmaf(kv.y, kv.y, kk.y);
        kk.z  = fmaf(kv.z, kv.z, kk.z);
        kk.w  = fmaf(kv.w, kv.w, kk.w);
        qq    = fmaf(qv, qv, qq);
    }

    const size_t pp = ((size_t)b * HP_ + h + 1) * WP_ + (w + 1);
    float4* o = reinterpret_cast<float4*>(g_nk + pp * D_ + sub * 4);
    o[0] = make_float4(num.x, kk.x, num.y, kk.y);
    o[1] = make_float4(num.z, kk.z, num.w, kk.w);
    if (sub == 0) g_qqp[pp] = qq;
}

// ---------------------------------------------------------------------------
// Kernel 2: 3x3 box of qq -> 1/max(sqrt, eps), one scalar per pixel.
// ---------------------------------------------------------------------------
__global__ __launch_bounds__(256)
void dav_nq(void)
{
    const int pix = blockIdx.x * 256 + threadIdx.x;
    if (pix >= NPIX) return;
    const int b  = pix / HW_;
    const int hw = pix - b * HW_;
    const int h  = hw / W_;
    const int w  = hw - h * W_;
    const float* __restrict__ c = g_qqp + ((size_t)b * HP_ + h + 1) * WP_ + (w + 1);

    float s = 0.f;
    #pragma unroll
    for (int dh = -1; dh <= 1; ++dh)
        #pragma unroll
        for (int dw = -1; dw <= 1; ++dw)
            s += c[dh * WP_ + dw];

    g_nqi[pix] = 1.f / fmaxf(sqrtf(s), EPS_);
}

// ---------------------------------------------------------------------------
// Kernel 3: 3x3 box of (num, kk) via sliding column sums + normalize.
// Block = 4 warps = 4 consecutive h over one 32-wide w tile. lane = d.
// Per output: 3 unconditional LDG.64 (constant offsets) + ~12 FADD.
// Shared [4][32][33] transpose -> each output write is one 128B warp store.
// ---------------------------------------------------------------------------
__global__ __launch_bounds__(128)
void dav_box_norm(float* __restrict__ out)
{
    __shared__ float s[4][32][33];

    const int lane = threadIdx.x & 31;          // = d
    const int wid  = threadIdx.x >> 5;          // h within tile: 0..3

    int t = blockIdx.x;
    const int wt = t % (W_ / 32);  t /= (W_ / 32);
    const int ht = t % (H_ / 4);   const int b = t / (H_ / 4);

    const int hb = ht * 4;             // tile base h
    const int h  = hb + wid;
    const int w0 = wt * 32;

    const int pitch = WP_ * D_;        // float2s per padded row
    const float2* __restrict__ base =
        g_nk + ((size_t)b * HP_ + h + 1) * WP_ * D_ + (size_t)w0 * D_ + lane;
    const float2* __restrict__ rm = base - pitch;   // row h-1 (padded)
    const float2* __restrict__ rc = base;           // row h
    const float2* __restrict__ rp = base + pitch;   // row h+1

    // column sum at padded column offset j (window cols = w0+j, j = 0..33)
    float2 c0, c1;
    {
        float2 a = rm[0],      c = rc[0],      e = rp[0];
        c0 = make_float2(a.x + c.x + e.x, a.y + c.y + e.y);
        a = rm[D_];  c = rc[D_];  e = rp[D_];
        c1 = make_float2(a.x + c.x + e.x, a.y + c.y + e.y);
    }

    const float* __restrict__ nqi_p = g_nqi + ((size_t)b * H_ + h) * W_ + w0;

    #pragma unroll
    for (int i = 0; i < 32; ++i) {
        const int j = (i + 2) * D_;
        const float2 a = rm[j], c = rc[j], e = rp[j];
        const float2 c2 = make_float2(a.x + c.x + e.x, a.y + c.y + e.y);

        const float num = c0.x + c1.x + c2.x;
        const float kk  = c0.y + c1.y + c2.y;
        const float sim = num * nqi_p[i] / fmaxf(sqrtf(kk), EPS_);
        s[wid][i][lane] = sim;

        c0 = c1; c1 = c2;
    }
    __syncthreads();

    // Write: 128 rows (d=0..31, hl=0..3), one 128B coalesced store each.
    const size_t obase = (size_t)b * D_ * HW_ + w0 + lane;
    #pragma unroll
    for (int i = 0; i < 32; ++i) {
        const int r  = i * 4 + wid;
        const int d  = r >> 2;
        const int hl = r & 3;
        out[obase + ((size_t)d * H_ + hb + hl) * W_] = s[hl][lane][d];
    }
}

// ---------------------------------------------------------------------------
extern "C" void kernel_launch(void* const* d_in, const int* in_sizes, int n_in,
                              void* d_out, int out_size)
{
    const float* q = (const float*)d_in[0];     // [B,C,H,W]
    const float* k = (const float*)d_in[1];     // [B,C,H,W,D]
    float* out     = (float*)d_out;             // [B,D,H,W]

    dav_zero_border<<<(B_ * 1028 + 127) / 128, 128>>>();
    dav_reduce_c<<<NPIX / 32, 256>>>(q, k);
    dav_nq<<<(NPIX + 255) / 256, 256>>>();
    dav_box_norm<<<B_ * (H_ / 4) * (W_ / 32), 128>>>(out);
}

// round 3
// speedup vs baseline: 1.1581x; 1.0520x over previous
#include <cuda_runtime.h>

// Shapes (fixed by the problem):
//   q:           [B=2, C=64, H=192, W=320]            fp32
//   warped_feat: [B=2, C=64, H=192, W=320, D=32]      fp32
//   out (sim):   [B=2, D=32, H=192, W=320]            fp32
#define B_  2
#define C_  64
#define H_  192
#define W_  320
#define D_  32
#define HW_ (H_ * W_)
#define NPIX (B_ * HW_)            // 122880
#define HP_ (H_ + 2)               // padded
#define WP_ (W_ + 2)
#define PPIX (B_ * HP_ * WP_)      // padded pixel count
#define EPS_ 1e-12f

// Scratch (zero-padded 1-pixel border so the 3x3 box needs no bounds checks).
// g_nk[pp][d] = (num, kk) interleaved -> one LDG.64 fetches both.
__device__ float2 g_nk [(size_t)PPIX * D_];    // ~32 MB (L2-resident)
__device__ float  g_qqp[PPIX];                 // padded sum_c q^2
__device__ float  g_nqi[NPIX];                 // 1 / max(sqrt(box(qq)), eps)

// ---------------------------------------------------------------------------
// Kernel 0: zero the padded border ring (1028 ring cells per image).
// ---------------------------------------------------------------------------
__global__ void dav_zero_border()
{
    const int t = blockIdx.x * 128 + threadIdx.x;
    if (t >= B_ * 1028) return;
    const int b = t / 1028;
    const int i = t - b * 1028;
    int hp, wp;
    if (i < WP_)          { hp = 0;       wp = i; }
    else if (i < 2 * WP_) { hp = H_ + 1;  wp = i - WP_; }
    else { const int j = i - 2 * WP_;     // j in [0, 2*H)
           hp = 1 + (j >> 1);  wp = (j & 1) ? (W_ + 1) : 0; }

    const size_t pp = ((size_t)b * HP_ + hp) * WP_ + wp;
    float4* o = reinterpret_cast<float4*>(g_nk + pp * D_);
    #pragma unroll
    for (int k = 0; k < 16; ++k) o[k] = make_float4(0.f, 0.f, 0.f, 0.f);
    g_qqp[pp] = 0.f;
}

// ---------------------------------------------------------------------------
// Kernel 1: per-pixel reduction over C (at HBM roofline; unchanged).
// 8 threads per pixel, float4 over d; writes interleaved (num,kk) float2s
// into the padded scratch.
// ---------------------------------------------------------------------------
__global__ __launch_bounds__(256, 4)
void dav_reduce_c(const float* __restrict__ q, const float* __restrict__ k)
{
    const int tid = threadIdx.x;
    const int grp = tid >> 3;          // pixel within block: 0..31
    const int sub = tid & 7;           // d-quad: 0..7
    const int pix = blockIdx.x * 32 + grp;

    const int b  = pix / HW_;
    const int hw = pix - b * HW_;
    const int h  = hw / W_;
    const int w  = hw - h * W_;

    const float* __restrict__ qp = q + (size_t)b * C_ * HW_ + hw;
    const float* __restrict__ kp = k + ((size_t)b * C_ * HW_ + hw) * D_ + sub * 4;

    float4 num = make_float4(0.f, 0.f, 0.f, 0.f);
    float4 kk  = make_float4(0.f, 0.f, 0.f, 0.f);
    float  qq  = 0.f;

    const size_t kstride = (size_t)HW_ * D_;

    #pragma unroll 8
    for (int c = 0; c < C_; ++c) {
        const float  qv = __ldg(qp + (size_t)c * HW_);
        const float4 kv = *reinterpret_cast<const float4*>(kp + (size_t)c * kstride);
        num.x = fmaf(qv, kv.x, num.x);
        num.y = fmaf(qv, kv.y, num.y);
        num.z = fmaf(qv, kv.z, num.z);
        num.w = fmaf(qv, kv.w, num.w);
        kk.x  = fmaf(kv.x, kv.x, kk.x);
        kk.y  = fmaf(kv.y, kv.y, kk.y);
        kk.z  = fmaf(kv.z, kv.z, kk.z);
        kk.w  = fmaf(kv.w, kv.w, kk.w);
        qq    = fmaf(qv, qv, qq);
    }

    const size_t pp = ((size_t)b * HP_ + h + 1) * WP_ + (w + 1);
    float4* o = reinterpret_cast<float4*>(g_nk + pp * D_ + sub * 4);
    o[0] = make_float4(num.x, kk.x, num.y, kk.y);
    o[1] = make_float4(num.z, kk.z, num.w, kk.w);
    if (sub == 0) g_qqp[pp] = qq;
}

// ---------------------------------------------------------------------------
// Kernel 2: 3x3 box of qq -> 1/max(sqrt, eps), one scalar per pixel.
// ---------------------------------------------------------------------------
__global__ __launch_bounds__(256)
void dav_nq(void)
{
    const int pix = blockIdx.x * 256 + threadIdx.x;
    if (pix >= NPIX) return;
    const int b  = pix / HW_;
    const int hw = pix - b * HW_;
    const int h  = hw / W_;
    const int w  = hw - h * W_;
    const float* __restrict__ c = g_qqp + ((size_t)b * HP_ + h + 1) * WP_ + (w + 1);

    float s = 0.f;
    #pragma unroll
    for (int dh = -1; dh <= 1; ++dh)
        #pragma unroll
        for (int dw = -1; dw <= 1; ++dw)
            s += c[dh * WP_ + dw];

    // 1/max(sqrt(s),eps) == rsqrt(max(s, eps^2))  (sqrt is monotone)
    g_nqi[pix] = rsqrtf(fmaxf(s, EPS_ * EPS_));
}

// ---------------------------------------------------------------------------
// Kernel 3: 3x3 box of (num, kk) via sliding column sums + normalize.
// Block = 4 warps = 4 consecutive h over one 16-wide w tile. lane = d.
// Halved tile (16 vs 32) doubles warp count -> occ 38% -> ~78% to cover
// load latency (kernel is latency-bound: all pipes <20% at R2).
// ---------------------------------------------------------------------------
__global__ __launch_bounds__(128)
void dav_box_norm(float* __restrict__ out)
{
    __shared__ float s[4][16][33];

    const int lane = threadIdx.x & 31;          // = d
    const int wid  = threadIdx.x >> 5;          // h within tile: 0..3

    int t = blockIdx.x;
    const int wt = t % (W_ / 16);  t /= (W_ / 16);
    const int ht = t % (H_ / 4);   const int b = t / (H_ / 4);

    const int hb = ht * 4;             // tile base h
    const int h  = hb + wid;
    const int w0 = wt * 16;

    const int pitch = WP_ * D_;        // float2s per padded row
    const float2* __restrict__ base =
        g_nk + ((size_t)b * HP_ + h + 1) * WP_ * D_ + (size_t)w0 * D_ + lane;
    const float2* __restrict__ rm = base - pitch;   // row h-1 (padded)
    const float2* __restrict__ rc = base;           // row h
    const float2* __restrict__ rp = base + pitch;   // row h+1

    // column sums at padded column offsets 0,1 (window cols w0-1, w0)
    float2 c0, c1;
    {
        float2 a = rm[0],      c = rc[0],      e = rp[0];
        c0 = make_float2(a.x + c.x + e.x, a.y + c.y + e.y);
        a = rm[D_];  c = rc[D_];  e = rp[D_];
        c1 = make_float2(a.x + c.x + e.x, a.y + c.y + e.y);
    }

    const float* __restrict__ nqi_p = g_nqi + ((size_t)b * H_ + h) * W_ + w0;

    #pragma unroll
    for (int i = 0; i < 16; ++i) {
        const int j = (i + 2) * D_;
        const float2 a = rm[j], c = rc[j], e = rp[j];
        const float2 c2 = make_float2(a.x + c.x + e.x, a.y + c.y + e.y);

        const float num = c0.x + c1.x + c2.x;
        const float kk  = c0.y + c1.y + c2.y;
        const float sim = num * nqi_p[i] * rsqrtf(fmaxf(kk, EPS_ * EPS_));
        s[wid][i][lane] = sim;

        c0 = c1; c1 = c2;
    }
    __syncthreads();

    // Write: 2048 outputs (4h x 16w x 32d), 16 stores/thread,
    // each warp store = 2 runs of 16 consecutive floats (64B each).
    const int ow = threadIdx.x & 15;        // w within tile
    const int rr = threadIdx.x >> 4;        // 0..7
    const size_t obase = (size_t)b * D_ * HW_ + w0 + ow;
    #pragma unroll
    for (int i = 0; i < 16; ++i) {
        const int idx = i * 8 + rr;         // 0..127 -> (d, hl)
        const int d   = idx >> 2;
        const int hl  = idx & 3;
        out[obase + ((size_t)d * H_ + hb + hl) * W_] = s[hl][ow][d];
    }
}

// ---------------------------------------------------------------------------
extern "C" void kernel_launch(void* const* d_in, const int* in_sizes, int n_in,
                              void* d_out, int out_size)
{
    const float* q = (const float*)d_in[0];     // [B,C,H,W]
    const float* k = (const float*)d_in[1];     // [B,C,H,W,D]
    float* out     = (float*)d_out;             // [B,D,H,W]

    dav_zero_border<<<(B_ * 1028 + 127) / 128, 128>>>();
    dav_reduce_c<<<NPIX / 32, 256>>>(q, k);
    dav_nq<<<(NPIX + 255) / 256, 256>>>();
    dav_box_norm<<<B_ * (H_ / 4) * (W_ / 16), 128>>>(out);
}

// round 4
// speedup vs baseline: 1.1871x; 1.0251x over previous
#include <cuda_runtime.h>

// Shapes (fixed by the problem):
//   q:           [B=2, C=64, H=192, W=320]            fp32
//   warped_feat: [B=2, C=64, H=192, W=320, D=32]      fp32
//   out (sim):   [B=2, D=32, H=192, W=320]            fp32
#define B_  2
#define C_  64
#define H_  192
#define W_  320
#define D_  32
#define HW_ (H_ * W_)
#define NPIX (B_ * HW_)            // 122880
#define HP_ (H_ + 2)               // padded
#define WP_ (W_ + 2)
#define PPIX (B_ * HP_ * WP_)      // padded pixel count
#define EPS2_ 1e-24f               // eps^2 for rsqrt(max(x, eps^2))

#define NB_MAIN   (NPIX / 32)      // 3840 main blocks in reduce_c
#define NBORDER   (B_ * 1028)      // ring cells to zero
#define NB_BORDER ((NBORDER + 255) / 256)   // 9 extra blocks

// Scratch (zero-padded 1-pixel border so the 3x3 box needs no bounds checks).
// g_nk[pp][d] = (num, kk) interleaved -> one LDG.64 fetches both.
__device__ float2 g_nk [(size_t)PPIX * D_];    // ~32 MB
__device__ float  g_qqp[PPIX];                 // padded sum_c q^2

// ---------------------------------------------------------------------------
// Kernel 1: per-pixel reduction over C (at HBM roofline).
// 8 threads per pixel, float4 over d. Trailing NB_BORDER blocks zero the
// padded border ring instead (fused to save a launch).
// ---------------------------------------------------------------------------
__global__ __launch_bounds__(256, 4)
void dav_reduce_c(const float* __restrict__ q, const float* __restrict__ k)
{
    if (blockIdx.x >= NB_MAIN) {
        // ---- border-zero path ----
        const int t = (blockIdx.x - NB_MAIN) * 256 + threadIdx.x;
        if (t >= NBORDER) return;
        const int b = t / 1028;
        const int i = t - b * 1028;
        int hp, wp;
        if (i < WP_)          { hp = 0;       wp = i; }
        else if (i < 2 * WP_) { hp = H_ + 1;  wp = i - WP_; }
        else { const int j = i - 2 * WP_;     // j in [0, 2*H)
               hp = 1 + (j >> 1);  wp = (j & 1) ? (W_ + 1) : 0; }

        const size_t pp = ((size_t)b * HP_ + hp) * WP_ + wp;
        float4* o = reinterpret_cast<float4*>(g_nk + pp * D_);
        #pragma unroll
        for (int m = 0; m < 16; ++m) o[m] = make_float4(0.f, 0.f, 0.f, 0.f);
        g_qqp[pp] = 0.f;
        return;
    }

    const int tid = threadIdx.x;
    const int grp = tid >> 3;          // pixel within block: 0..31
    const int sub = tid & 7;           // d-quad: 0..7
    const int pix = blockIdx.x * 32 + grp;

    const int b  = pix / HW_;
    const int hw = pix - b * HW_;
    const int h  = hw / W_;
    const int w  = hw - h * W_;

    const float* __restrict__ qp = q + (size_t)b * C_ * HW_ + hw;
    const float* __restrict__ kp = k + ((size_t)b * C_ * HW_ + hw) * D_ + sub * 4;

    float4 num = make_float4(0.f, 0.f, 0.f, 0.f);
    float4 kk  = make_float4(0.f, 0.f, 0.f, 0.f);
    float  qq  = 0.f;

    const size_t kstride = (size_t)HW_ * D_;

    #pragma unroll 8
    for (int c = 0; c < C_; ++c) {
        const float  qv = __ldg(qp + (size_t)c * HW_);
        const float4 kv = *reinterpret_cast<const float4*>(kp + (size_t)c * kstride);
        num.x = fmaf(qv, kv.x, num.x);
        num.y = fmaf(qv, kv.y, num.y);
        num.z = fmaf(qv, kv.z, num.z);
        num.w = fmaf(qv, kv.w, num.w);
        kk.x  = fmaf(kv.x, kv.x, kk.x);
        kk.y  = fmaf(kv.y, kv.y, kk.y);
        kk.z  = fmaf(kv.z, kv.z, kk.z);
        kk.w  = fmaf(kv.w, kv.w, kk.w);
        qq    = fmaf(qv, qv, qq);
    }

    const size_t pp = ((size_t)b * HP_ + h + 1) * WP_ + (w + 1);
    float4* o = reinterpret_cast<float4*>(g_nk + pp * D_ + sub * 4);
    o[0] = make_float4(num.x, kk.x, num.y, kk.y);
    o[1] = make_float4(num.z, kk.z, num.w, kk.w);
    if (sub == 0) g_qqp[pp] = qq;
}

// ---------------------------------------------------------------------------
// Kernel 2: 3x3 box + normalize, nq fused.
// Block = 4 warps = 4 consecutive h over one 16-wide w tile; lane = d.
// Phase A: all 18 column sums computed in one unrolled pass -> 54 independent
//          LDG.64 in flight per warp (MLP ~ M_max) hides the full memory
//          latency once, instead of 16 serialized round-trips.
//          qq column sums are lane-invariant (broadcast loads / uniform regs).
// Phase B: pure-register sliding sums + rsqrt epilogue.
// Phase C: shared transpose -> coalesced [b,d,h,w] stores.
// ---------------------------------------------------------------------------
__global__ __launch_bounds__(128)
void dav_box_norm(float* __restrict__ out)
{
    __shared__ float s[4][16][33];

    const int lane = threadIdx.x & 31;          // = d
    const int wid  = threadIdx.x >> 5;          // h within tile: 0..3

    int t = blockIdx.x;
    const int wt = t % (W_ / 16);  t /= (W_ / 16);
    const int ht = t % (H_ / 4);   const int b = t / (H_ / 4);

    const int hb = ht * 4;             // tile base h
    const int h  = hb + wid;
    const int w0 = wt * 16;

    const int pitch = WP_ * D_;        // float2s per padded row
    const float2* __restrict__ base =
        g_nk + (((size_t)b * HP_ + h + 1) * WP_ + w0) * D_ + lane;
    const float* __restrict__ qb =
        g_qqp + ((size_t)b * HP_ + h + 1) * WP_ + w0;

    // Phase A: column sums for the 18 padded columns covering outputs w0..w0+15.
    float2 cs[18];
    float  qs[18];
    #pragma unroll
    for (int j = 0; j < 18; ++j) {
        const int o = j * D_;
        const float2 a = base[o - pitch];
        const float2 c = base[o];
        const float2 e = base[o + pitch];
        cs[j] = make_float2(a.x + c.x + e.x, a.y + c.y + e.y);
        qs[j] = qb[j - WP_] + qb[j] + qb[j + WP_];
    }

    // Phase B: sliding 3-column sums + normalize.
    #pragma unroll
    for (int i = 0; i < 16; ++i) {
        const float num = cs[i].x + cs[i + 1].x + cs[i + 2].x;
        const float kk  = cs[i].y + cs[i + 1].y + cs[i + 2].y;
        const float qq  = qs[i]   + qs[i + 1]   + qs[i + 2];
        s[wid][i][lane] = num * rsqrtf(fmaxf(qq, EPS2_))
                              * rsqrtf(fmaxf(kk, EPS2_));
    }
    __syncthreads();

    // Phase C: 2048 outputs (4h x 16w x 32d), 16 stores/thread, each warp
    // store = 2 runs of 16 consecutive floats.
    const int ow = threadIdx.x & 15;        // w within tile
    const int rr = threadIdx.x >> 4;        // 0..7
    const size_t obase = (size_t)b * D_ * HW_ + w0 + ow;
    #pragma unroll
    for (int i = 0; i < 16; ++i) {
        const int idx = i * 8 + rr;         // 0..127 -> (d, hl)
        const int d   = idx >> 2;
        const int hl  = idx & 3;
        out[obase + ((size_t)d * H_ + hb + hl) * W_] = s[hl][ow][d];
    }
}

// ---------------------------------------------------------------------------
extern "C" void kernel_launch(void* const* d_in, const int* in_sizes, int n_in,
                              void* d_out, int out_size)
{
    const float* q = (const float*)d_in[0];     // [B,C,H,W]
    const float* k = (const float*)d_in[1];     // [B,C,H,W,D]
    float* out     = (float*)d_out;             // [B,D,H,W]

    dav_reduce_c<<<NB_MAIN + NB_BORDER, 256>>>(q, k);
    dav_box_norm<<<B_ * (H_ / 4) * (W_ / 16), 128>>>(out);
}